// round 11
// baseline (speedup 1.0000x reference)
#include <cuda_runtime.h>
#include <cstdint>

// Shapes:
//   x0:     (B=4, N=512, 3)          float32
//   params: (B=4, T=96, N=512, 514)  float32
// d_out = output_view (B,T,N,3) ++ epiparams (B,T,N,514)

#define BB 4
#define TT 96
#define NN 512
#define PROW 514
#define EPSV 1e-8f

#define BLOCKS_PER_GROUP 32
#define THREADS 512
#define WARPS 16
#define OUT_VIEW_ELEMS (BB * TT * NN * 3)   // 589824

// ---- global scratch (static; no allocation) ----
__device__ unsigned g_count[BB];
__device__ unsigned g_release[BB];
__device__ float g_xI[2][BB][NN];   // double-buffered infected vector

__global__ void reset_kernel() {
    if (threadIdx.x < BB) {
        g_count[threadIdx.x]   = 0u;
        g_release[threadIdx.x] = 0u;
    }
}

__device__ __forceinline__ void load_row(const float* __restrict__ params,
                                         size_t rindex, int lane,
                                         float2 v[8], float& p01) {
    const float* prow = params + rindex * (size_t)PROW;
    p01 = (lane < 2) ? prow[lane] : 0.0f;
    // prow+2 is 8-byte aligned for every row (row stride 2056 B, +8).
    const float2* prow2 = reinterpret_cast<const float2*>(prow + 2);
#pragma unroll
    for (int k = 0; k < 8; ++k) v[k] = prow2[lane + 32 * k];
}

__global__ void __launch_bounds__(THREADS, 1)
ssir_kernel(const float* __restrict__ x0,
            const float* __restrict__ params,
            float* __restrict__ out) {
    __shared__ float I_s[NN];
    float2* I_s2 = reinterpret_cast<float2*>(I_s);

    const int b    = blockIdx.y;
    const int warp = threadIdx.x >> 5;
    const int lane = threadIdx.x & 31;
    const int n    = blockIdx.x * WARPS + warp;   // row owned by this warp

    float* outv = out;                   // output_view region
    float* oute = out + OUT_VIEW_ELEMS;  // epiparams region

    const size_t rbase = ((size_t)b * TT) * NN + (size_t)n;

    // Scan state lives in registers (redundant across lanes).
    const float* xr = x0 + ((size_t)b * NN + n) * 3;
    float S  = xr[0];
    float Iv = xr[1];
    float R  = xr[2];

    // Prefetch t=0 params row.
    float2 v[8];
    float p01;
    load_row(params, rbase, lane, v, p01);

    for (int t = 0; t < TT; ++t) {
        // ---------- SHADOW WORK (scan-independent) ----------
        float p0 = __shfl_sync(0xffffffffu, p01, 0);
        float p1 = __shfl_sync(0xffffffffu, p01, 1);
        float beta  = 1.0f / (1.0f + __expf(-p0));
        float gamma = 1.0f / (1.0f + __expf(-p1));

        float m = -1e30f;
#pragma unroll
        for (int k = 0; k < 8; ++k) m = fmaxf(m, fmaxf(v[k].x, v[k].y));
#pragma unroll
        for (int off = 16; off; off >>= 1)
            m = fmaxf(m, __shfl_xor_sync(0xffffffffu, m, off));

        float sum = 0.0f;
#pragma unroll
        for (int k = 0; k < 8; ++k) {
            v[k].x = __expf(v[k].x - m);
            v[k].y = __expf(v[k].y - m);
            sum += v[k].x + v[k].y;
        }
#pragma unroll
        for (int off = 16; off; off >>= 1)
            sum += __shfl_xor_sync(0xffffffffu, sum, off);
        float inv = 1.0f / sum;
#pragma unroll
        for (int k = 0; k < 8; ++k) { v[k].x *= inv; v[k].y *= inv; }

        // Prefetch next params row (issued before the barrier wait so DRAM
        // latency is absorbed by the wait).
        float2 vn[8];
        float p01n = 0.0f;
        if (t + 1 < TT)
            load_row(params, rbase + (size_t)(t + 1) * NN, lane, vn, p01n);

        // Stream out the epiparams row (independent of the scan).
        const size_t rindex = rbase + (size_t)t * NN;
        float* erow = oute + rindex * (size_t)PROW;
        if (lane == 0)
            *reinterpret_cast<float2*>(erow) = make_float2(beta, gamma);
        float2* erow2 = reinterpret_cast<float2*>(erow + 2);
#pragma unroll
        for (int k = 0; k < 8; ++k)
            erow2[lane + 32 * k] = v[k];

        // ---------- CRITICAL PATH ----------
        if (t > 0) {
            if (threadIdx.x == 0) {
                unsigned r;
                for (;;) {
                    asm volatile("ld.acquire.gpu.global.u32 %0, [%1];"
                                 : "=r"(r) : "l"(&g_release[b]) : "memory");
                    if (r >= (unsigned)t) break;
                    __nanosleep(20);
                }
            }
            __syncthreads();
            I_s[threadIdx.x] = g_xI[t & 1][b][threadIdx.x];
        } else {
            I_s[threadIdx.x] = x0[((size_t)b * NN + threadIdx.x) * 3 + 1];
        }
        __syncthreads();

        // infection_n = c_n . I_t  (softmax already normalized in v)
        float dot = 0.0f;
#pragma unroll
        for (int k = 0; k < 8; ++k) {
            float2 iv = I_s2[lane + 32 * k];
            dot += v[k].x * iv.x + v[k].y * iv.y;
        }
#pragma unroll
        for (int off = 16; off; off >>= 1)
            dot += __shfl_xor_sync(0xffffffffu, dot, off);
        float infection = dot;

        float Npop = fmaxf(S + Iv + R, EPSV);
        float dS = -((beta * S) / Npop) * infection;
        float gI = gamma * Iv;
        float St = fmaxf(S + dS, 0.0f);
        float It = fmaxf(Iv - dS - gI, 0.0f);
        float Rt = fmaxf(R + gI, 0.0f);
        float scale = Npop / fmaxf(St + It + Rt, EPSV);
        S  = St * scale;
        Iv = It * scale;
        R  = Rt * scale;

        if (lane == 0) {
            float* orow = outv + rindex * 3;
            orow[0] = S;
            orow[1] = Iv;
            orow[2] = Rt * scale;
            if (t + 1 < TT)
                g_xI[(t + 1) & 1][b][n] = Iv;
        }

        if (t + 1 < TT) {
            __syncthreads();                 // all warps' I writes issued
            if (threadIdx.x == 0) {
                __threadfence();             // publish I_{t+1}
                unsigned a = atomicAdd(&g_count[b], 1u) + 1u;
                if (a == (unsigned)(t + 1) * (unsigned)BLOCKS_PER_GROUP) {
                    __threadfence();
                    atomicExch(&g_release[b], (unsigned)(t + 1));
                }
            }
        }

#pragma unroll
        for (int k = 0; k < 8; ++k) v[k] = vn[k];
        p01 = p01n;
    }
}

extern "C" void kernel_launch(void* const* d_in, const int* in_sizes, int n_in,
                              void* d_out, int out_size) {
    (void)in_sizes; (void)n_in; (void)out_size;
    const float* x0     = (const float*)d_in[0];
    const float* params = (const float*)d_in[1];
    float* out = (float*)d_out;

    reset_kernel<<<1, 32>>>();

    dim3 grid(BLOCKS_PER_GROUP, BB);
    ssir_kernel<<<grid, THREADS>>>(x0, params, out);
}

// round 12
// speedup vs baseline: 1.2899x; 1.2899x over previous
#include <cuda_runtime.h>
#include <cstdint>

// Shapes:
//   x0:     (B=4, N=512, 3)          float32
//   params: (B=4, T=96, N=512, 514)  float32
// d_out = output_view (B,T,N,3) ++ epiparams (B,T,N,514)

#define BB 4
#define TT 96
#define NN 512
#define PROW 514
#define EPSV 1e-8f

#define BLOCKS_PER_GROUP 32
#define THREADS 512
#define WARPS 16
#define OUT_VIEW_ELEMS (BB * TT * NN * 3)   // 589824

// ---- global scratch (static; no allocation) ----
__device__ unsigned g_flag[BB][BLOCKS_PER_GROUP];  // per-block epoch flags
__device__ float g_xI[2][BB][NN];                  // double-buffered I vector

__global__ void reset_kernel() {
    if (threadIdx.x < BB * BLOCKS_PER_GROUP)
        reinterpret_cast<unsigned*>(g_flag)[threadIdx.x] = 0u;
}

__device__ __forceinline__ void load_row(const float* __restrict__ params,
                                         size_t rindex, int lane,
                                         float2 v[8], float& p01) {
    const float* prow = params + rindex * (size_t)PROW;
    p01 = (lane < 2) ? prow[lane] : 0.0f;
    // prow+2 is 8-byte aligned for every row (row stride 2056 B, +8).
    const float2* prow2 = reinterpret_cast<const float2*>(prow + 2);
#pragma unroll
    for (int k = 0; k < 8; ++k) v[k] = prow2[lane + 32 * k];
}

__global__ void __launch_bounds__(THREADS, 1)
ssir_kernel(const float* __restrict__ x0,
            const float* __restrict__ params,
            float* __restrict__ out) {
    __shared__ float I_s[NN];
    float2* I_s2 = reinterpret_cast<float2*>(I_s);

    const int b    = blockIdx.y;
    const int blk  = blockIdx.x;
    const int warp = threadIdx.x >> 5;
    const int lane = threadIdx.x & 31;
    const int n    = blk * WARPS + warp;   // row owned by this warp

    float* outv = out;                   // output_view region
    float* oute = out + OUT_VIEW_ELEMS;  // epiparams region

    const size_t rbase = ((size_t)b * TT) * NN + (size_t)n;

    // Scan state lives in registers (redundant across lanes).
    const float* xr = x0 + ((size_t)b * NN + n) * 3;
    float S  = xr[0];
    float Iv = xr[1];
    float R  = xr[2];

    // Prefetch t=0 params row.
    float2 v[8];
    float p01;
    load_row(params, rbase, lane, v, p01);

    for (int t = 0; t < TT; ++t) {
        // ---------- prefetch t+1 FIRST: maximize load in-flight time ----------
        float2 vn[8];
        float p01n = 0.0f;
        if (t + 1 < TT)
            load_row(params, rbase + (size_t)(t + 1) * NN, lane, vn, p01n);

        // ---------- shadow work (scan-independent) ----------
        float p0 = __shfl_sync(0xffffffffu, p01, 0);
        float p1 = __shfl_sync(0xffffffffu, p01, 1);
        float beta  = 1.0f / (1.0f + __expf(-p0));
        float gamma = 1.0f / (1.0f + __expf(-p1));

        float m = -1e30f;
#pragma unroll
        for (int k = 0; k < 8; ++k) m = fmaxf(m, fmaxf(v[k].x, v[k].y));
#pragma unroll
        for (int off = 16; off; off >>= 1)
            m = fmaxf(m, __shfl_xor_sync(0xffffffffu, m, off));

        float sum = 0.0f;
#pragma unroll
        for (int k = 0; k < 8; ++k) {
            v[k].x = __expf(v[k].x - m);
            v[k].y = __expf(v[k].y - m);
            sum += v[k].x + v[k].y;
        }
#pragma unroll
        for (int off = 16; off; off >>= 1)
            sum += __shfl_xor_sync(0xffffffffu, sum, off);
        float inv = 1.0f / sum;
#pragma unroll
        for (int k = 0; k < 8; ++k) { v[k].x *= inv; v[k].y *= inv; }

        // Stream out the epiparams row (independent of the scan).
        const size_t rindex = rbase + (size_t)t * NN;
        float* erow = oute + rindex * (size_t)PROW;
        if (lane == 0)
            *reinterpret_cast<float2*>(erow) = make_float2(beta, gamma);
        float2* erow2 = reinterpret_cast<float2*>(erow + 2);
#pragma unroll
        for (int k = 0; k < 8; ++k)
            erow2[lane + 32 * k] = v[k];

        // ---------- critical path ----------
        if (t > 0) {
            // Vector flag poll: one coalesced 128-B acquire load per iteration
            // covers all 32 producer flags.
            if (warp == 0) {
                unsigned r;
                do {
                    asm volatile("ld.acquire.gpu.global.u32 %0, [%1];"
                                 : "=r"(r)
                                 : "l"(&g_flag[b][lane]) : "memory");
                } while (__any_sync(0xffffffffu, r < (unsigned)t));
            }
            __syncthreads();
            I_s[threadIdx.x] = g_xI[t & 1][b][threadIdx.x];
        } else {
            I_s[threadIdx.x] = x0[((size_t)b * NN + threadIdx.x) * 3 + 1];
        }
        __syncthreads();

        // infection_n = softmax(c)_n . I_t
        float dot = 0.0f;
#pragma unroll
        for (int k = 0; k < 8; ++k) {
            float2 iv = I_s2[lane + 32 * k];
            dot += v[k].x * iv.x + v[k].y * iv.y;
        }
#pragma unroll
        for (int off = 16; off; off >>= 1)
            dot += __shfl_xor_sync(0xffffffffu, dot, off);
        float infection = dot;

        float Npop = fmaxf(S + Iv + R, EPSV);
        float dS = -((beta * S) / Npop) * infection;
        float gI = gamma * Iv;
        float St = fmaxf(S + dS, 0.0f);
        float It = fmaxf(Iv - dS - gI, 0.0f);
        float Rt = fmaxf(R + gI, 0.0f);
        float scale = Npop / fmaxf(St + It + Rt, EPSV);
        S  = St * scale;
        Iv = It * scale;
        R  = Rt * scale;

        // output_view row: 3 lanes store in parallel
        if (lane < 3) {
            float ov = (lane == 0) ? S : ((lane == 1) ? Iv : R);
            outv[rindex * 3 + lane] = ov;
        }
        if (lane == 0 && t + 1 < TT)
            g_xI[(t + 1) & 1][b][n] = Iv;

        if (t + 1 < TT) {
            __syncthreads();                 // all warps' I writes issued
            if (threadIdx.x == 0) {
                __threadfence();             // publish I_{t+1} (all threads' stores)
                asm volatile("st.release.gpu.global.u32 [%0], %1;"
                             :: "l"(&g_flag[b][blk]), "r"((unsigned)(t + 1))
                             : "memory");
            }
        }

#pragma unroll
        for (int k = 0; k < 8; ++k) v[k] = vn[k];
        p01 = p01n;
    }
}

extern "C" void kernel_launch(void* const* d_in, const int* in_sizes, int n_in,
                              void* d_out, int out_size) {
    (void)in_sizes; (void)n_in; (void)out_size;
    const float* x0     = (const float*)d_in[0];
    const float* params = (const float*)d_in[1];
    float* out = (float*)d_out;

    reset_kernel<<<1, 128>>>();

    dim3 grid(BLOCKS_PER_GROUP, BB);
    ssir_kernel<<<grid, THREADS>>>(x0, params, out);
}